// round 1
// baseline (speedup 1.0000x reference)
#include <cuda_runtime.h>

// RasterizePointsXYsBlending — brute-force per-pixel scan baseline.
// B=2, P=2048, C=64, SIZE=128, K=8, RADIUS=1.5px, RAD_POW=2, TAU=1.
//
// Layout: one thread per pixel. block = 128 threads = one image row (w = tid),
// grid = B*SIZE blocks (b = blk>>7, h = blk&127). All 2048 points for the
// batch staged in shared memory as float4 (x,y pre-flipped), broadcast-read.

#define BN 2
#define PN 2048
#define CN 64
#define SZ 128
#define KN 8
#define BIGF 1e10f
// r_ndc = 1.5/128*2 = 3*2^-7 ; r2 = 9*2^-14 (exact fp32)
#define R2 0.00054931640625f

__global__ __launch_bounds__(128)
void raster_points_kernel(const float* __restrict__ pts,
                          const float* __restrict__ src,
                          float* __restrict__ out)
{
    __shared__ float4 sp[PN];   // 32 KB

    const int w = threadIdx.x;
    const int h = blockIdx.x & (SZ - 1);
    const int b = blockIdx.x >> 7;

    // Stage points for this batch into smem, applying the xy sign flip.
    const float* pb = pts + (size_t)b * PN * 3;
    for (int p = threadIdx.x; p < PN; p += 128) {
        float x = pb[p * 3 + 0];
        float y = pb[p * 3 + 1];
        float z = pb[p * 3 + 2];
        sp[p] = make_float4(-x, -y, z, 0.0f);
    }
    __syncthreads();

    // Pixel-center NDC coords (pytorch3d convention).
    const float ndcx = 1.0f - (2.0f * (float)w + 1.0f) / 128.0f;
    const float ndcy = 1.0f - (2.0f * (float)h + 1.0f) / 128.0f;

    // Register-resident top-K (sorted ascending by z).
    float zb[KN], db[KN];
    int   ib[KN];
#pragma unroll
    for (int k = 0; k < KN; ++k) { zb[k] = BIGF; db[k] = 0.0f; ib[k] = 0; }

#pragma unroll 4
    for (int p = 0; p < PN; ++p) {
        float4 pt = sp[p];
        float dx = ndcx - pt.x;
        float dy = ndcy - pt.y;
        // Non-fused to match the reference's mul/mul/add rounding exactly
        // (the radius test is a hard discontinuity).
        float d2 = __fadd_rn(__fmul_rn(dx, dx), __fmul_rn(dy, dy));
        if (d2 <= R2 && pt.z < zb[KN - 1]) {
            float cz = pt.z, cd = d2;
            int   ci = p;
            bool  ins = false;
#pragma unroll
            for (int k = 0; k < KN; ++k) {
                bool sw = ins | (cz < zb[k]);
                if (sw) {
                    float tz = zb[k]; zb[k] = cz; cz = tz;
                    float td = db[k]; db[k] = cd; cd = td;
                    int   ti = ib[k]; ib[k] = ci; ci = ti;
                    ins = true;
                }
            }
        }
    }

    // Compositing weights: w_k = a_k * prod_{j<k}(1 - a_j), front-to-back.
    float wk[KN];
    float T = 1.0f;
#pragma unroll
    for (int k = 0; k < KN; ++k) {
        if (zb[k] < BIGF) {
            float dist = __fdiv_rn(db[k], R2);
            dist = fminf(fmaxf(dist, 0.001f), 1.0f);
            float a = 1.0f - __fsqrt_rn(dist);
            wk[k] = a * T;
            T = T * (1.0f - a);
        } else {
            wk[k] = 0.0f;
        }
    }

    // Feature gather + accumulate. src[b,c,p]; out[b,c,h,w].
    const float* sb = src + (size_t)b * CN * PN;
    float* ob = out + (((size_t)b * CN) * SZ + h) * SZ + w;

#pragma unroll 4
    for (int c = 0; c < CN; ++c) {
        float acc = 0.0f;
        const float* sc = sb + c * PN;
#pragma unroll
        for (int k = 0; k < KN; ++k) {
            if (wk[k] > 0.0f) acc = fmaf(wk[k], sc[ib[k]], acc);
        }
        ob[(size_t)c * SZ * SZ] = acc;
    }
}

extern "C" void kernel_launch(void* const* d_in, const int* in_sizes, int n_in,
                              void* d_out, int out_size)
{
    const float* pts = (const float*)d_in[0];  // [B,P,3] fp32
    const float* src = (const float*)d_in[1];  // [B,C,P] fp32
    float* out = (float*)d_out;                // [B,C,H,W] fp32

    dim3 grid(BN * SZ);
    dim3 block(128);
    raster_points_kernel<<<grid, block>>>(pts, src, out);
}

// round 2
// speedup vs baseline: 3.6519x; 3.6519x over previous
#include <cuda_runtime.h>

// RasterizePointsXYsBlending — tile-binned version.
// B=2, P=2048, C=64, SIZE=128, K=8, RADIUS=1.5px, RAD_POW=2, TAU=1.
//
// 3 kernels:
//  1. prep:   transpose src [B,C,P] -> srcT [B,P,C]; zero bin counters.
//  2. bin:    append each point to the 32x8-pixel tile bins its radius touches.
//  3. raster: per tile, exact inside-test + register top-8 by z + composite.

#define BN 2
#define PN 2048
#define CN 64
#define SZ 128
#define KN 8
#define BIGF 1e10f
// r_ndc = 1.5/128*2 = 3*2^-7 ; r2 = 9*2^-14 (exact fp32)
#define R2 0.00054931640625f

#define TW 32              // tile width  (pixels)
#define TH 8               // tile height (pixels)
#define NTX (SZ / TW)      // 4
#define NTY (SZ / TH)      // 16
#define NT  (NTX * NTY)    // 64 tiles per image
#define CAP 512            // bin capacity (expected load ~48)

__device__ int    d_cnt[BN * NT];
__device__ float4 d_bins[BN * NT * CAP];   // (x, y, z, bitcast idx)
__device__ float  d_srcT[BN * PN * CN];    // src transposed to [b,p,c]

// ---------------------------------------------------------------- kernel 1
__global__ __launch_bounds__(256)
void prep_kernel(const float* __restrict__ src)
{
    if (blockIdx.x == 0 && threadIdx.x < BN * NT) d_cnt[threadIdx.x] = 0;

    int stride = gridDim.x * blockDim.x;
    for (int i = blockIdx.x * blockDim.x + threadIdx.x;
         i < BN * PN * CN; i += stride) {
        int c = i & (CN - 1);
        int p = (i >> 6) & (PN - 1);
        int b = i >> 17;                       // 6 bits c + 11 bits p
        d_srcT[i] = src[((b * CN + c) << 11) + p];
    }
}

// ---------------------------------------------------------------- kernel 2
__global__ __launch_bounds__(256)
void bin_kernel(const float* __restrict__ pts)
{
    int g = blockIdx.x * blockDim.x + threadIdx.x;
    if (g >= BN * PN) return;
    int b = g >> 11;
    int p = g & (PN - 1);

    float px = -pts[g * 3 + 0];   // sign flip from the forward
    float py = -pts[g * 3 + 1];
    float pz =  pts[g * 3 + 2];

    // pixel-space center of the point: ndcx(w) = 1 - (2w+1)/128
    float u = (1.0f - px) * 64.0f - 0.5f;   // w coordinate
    float v = (1.0f - py) * 64.0f - 0.5f;   // h coordinate

    // conservative 1.5px radius + 0.1px fp margin
    int tx_lo = max(0,       (int)floorf((u - 1.6f) * (1.0f / TW)));
    int tx_hi = min(NTX - 1, (int)floorf((u + 1.6f) * (1.0f / TW)));
    int ty_lo = max(0,       (int)floorf((v - 1.6f) * (1.0f / TH)));
    int ty_hi = min(NTY - 1, (int)floorf((v + 1.6f) * (1.0f / TH)));

    float4 e = make_float4(px, py, pz, __int_as_float(p));
    for (int ty = ty_lo; ty <= ty_hi; ++ty)
        for (int tx = tx_lo; tx <= tx_hi; ++tx) {
            int t = b * NT + ty * NTX + tx;
            int slot = atomicAdd(&d_cnt[t], 1);
            if (slot < CAP) d_bins[t * CAP + slot] = e;
        }
}

// ---------------------------------------------------------------- kernel 3
__global__ __launch_bounds__(256)
void raster_kernel(float* __restrict__ out)
{
    __shared__ float4 sp[CAP];   // 8 KB

    const int b    = blockIdx.x >> 6;
    const int t    = blockIdx.x & (NT - 1);
    const int ty   = t >> 2;
    const int tx   = t & (NTX - 1);
    const int lane = threadIdx.x & (TW - 1);
    const int row  = threadIdx.x >> 5;
    const int w    = tx * TW + lane;
    const int h    = ty * TH + row;

    const int cnt = min(d_cnt[b * NT + t], CAP);
    const float4* bp = d_bins + (b * NT + t) * CAP;
    for (int i = threadIdx.x; i < cnt; i += 256) sp[i] = bp[i];
    __syncthreads();

    const float ndcx = 1.0f - (2.0f * (float)w + 1.0f) / 128.0f;
    const float ndcy = 1.0f - (2.0f * (float)h + 1.0f) / 128.0f;

    // register top-K sorted ascending by z
    float zb[KN], db[KN];
    int   ib[KN];
#pragma unroll
    for (int k = 0; k < KN; ++k) { zb[k] = BIGF; db[k] = 0.0f; ib[k] = 0; }

    for (int i = 0; i < cnt; ++i) {
        float4 pt = sp[i];
        float dx = ndcx - pt.x;
        float dy = ndcy - pt.y;
        // non-fused: match reference rounding at the radius discontinuity
        float d2 = __fadd_rn(__fmul_rn(dx, dx), __fmul_rn(dy, dy));
        if (d2 <= R2 && pt.z < zb[KN - 1]) {
            float cz = pt.z, cd = d2;
            int   ci = __float_as_int(pt.w);
            bool  ins = false;
#pragma unroll
            for (int k = 0; k < KN; ++k) {
                bool sw = ins | (cz < zb[k]);
                if (sw) {
                    float tz = zb[k]; zb[k] = cz; cz = tz;
                    float td = db[k]; db[k] = cd; cd = td;
                    int   ti = ib[k]; ib[k] = ci; ci = ti;
                    ins = true;
                }
            }
        }
    }

    // compositing weights: w_k = a_k * prod_{j<k}(1 - a_j)
    float wk[KN];
    float T = 1.0f;
#pragma unroll
    for (int k = 0; k < KN; ++k) {
        if (zb[k] < BIGF) {
            float dist = __fdiv_rn(db[k], R2);
            dist = fminf(fmaxf(dist, 0.001f), 1.0f);
            float a = 1.0f - __fsqrt_rn(dist);
            wk[k] = a * T;
            T = T * (1.0f - a);
        } else {
            wk[k] = 0.0f;
        }
    }

    // feature gather from transposed src (contiguous 64 floats per point)
    float acc[CN];
#pragma unroll
    for (int c = 0; c < CN; ++c) acc[c] = 0.0f;

#pragma unroll
    for (int k = 0; k < KN; ++k) {
        if (wk[k] > 0.0f) {
            const float4* s4 =
                (const float4*)(d_srcT + (((size_t)b * PN + ib[k]) << 6));
            float wkk = wk[k];
#pragma unroll
            for (int j = 0; j < CN / 4; ++j) {
                float4 v = s4[j];
                acc[4 * j + 0] = fmaf(wkk, v.x, acc[4 * j + 0]);
                acc[4 * j + 1] = fmaf(wkk, v.y, acc[4 * j + 1]);
                acc[4 * j + 2] = fmaf(wkk, v.z, acc[4 * j + 2]);
                acc[4 * j + 3] = fmaf(wkk, v.w, acc[4 * j + 3]);
            }
        }
    }

    // out[b,c,h,w]; warp = one 32-px row -> fully coalesced 128B stores
    float* ob = out + (((size_t)b * CN) * SZ + h) * SZ + w;
#pragma unroll
    for (int c = 0; c < CN; ++c)
        ob[(size_t)c * SZ * SZ] = acc[c];
}

// ---------------------------------------------------------------- launch
extern "C" void kernel_launch(void* const* d_in, const int* in_sizes, int n_in,
                              void* d_out, int out_size)
{
    const float* pts = (const float*)d_in[0];  // [B,P,3]
    const float* src = (const float*)d_in[1];  // [B,C,P]
    float* out = (float*)d_out;                // [B,C,H,W]

    prep_kernel<<<256, 256>>>(src);
    bin_kernel<<<(BN * PN + 255) / 256, 256>>>(pts);
    raster_kernel<<<BN * NT, 256>>>(out);
}

// round 3
// speedup vs baseline: 4.0202x; 1.1008x over previous
#include <cuda_runtime.h>

// RasterizePointsXYsBlending — 2-kernel version.
// B=2, P=2048, C=64, SIZE=128, K=8, RADIUS=1.5px, RAD_POW=2, TAU=1.
//
//  1. transpose: src [B,C,P] -> srcT [B,P,C], coalesced both sides (smem tile).
//  2. raster:    per 32x4 tile block: scan all points, bbox-test, smem
//                candidate list, exact inside-test + register top-8 by z,
//                composite, gather features from srcT, coalesced stores.

#define BN 2
#define PN 2048
#define CN 64
#define SZ 128
#define KN 8
#define BIGF 1e10f
// r_ndc = 1.5/128*2 = 3*2^-7 ; r2 = 9*2^-14 (exact fp32)
#define R2  0.00054931640625f
#define RAD 0.0234375f
#define RADM 0.0236f          // conservative margin for bbox cull

#define TW 32                 // tile width (pixels)
#define TH 4                  // tile height (pixels)
#define NTX (SZ / TW)         // 4
#define NTY (SZ / TH)         // 32
#define NT  (NTX * NTY)       // 128 tiles per image
#define CAP 512               // candidate list capacity (expected ~30)

__device__ float d_srcT[BN * PN * CN];   // src transposed to [b,p,c]

// ---------------------------------------------------------------- kernel 1
// 32x32 tile transpose, block (32,8). grid (P/32, C/32, B).
__global__ __launch_bounds__(256)
void transpose_kernel(const float* __restrict__ src)
{
    __shared__ float t[32][33];

    const int p0 = blockIdx.x * 32;
    const int c0 = blockIdx.y * 32;
    const int b  = blockIdx.z;
    const int x  = threadIdx.x;
    const int y  = threadIdx.y;

    const float* sb = src + ((size_t)b * CN << 11);
#pragma unroll
    for (int j = 0; j < 4; ++j)
        t[y + 8 * j][x] = sb[((size_t)(c0 + y + 8 * j) << 11) + p0 + x];
    __syncthreads();

    float* db = d_srcT + (((size_t)b * PN) << 6);
#pragma unroll
    for (int j = 0; j < 4; ++j)
        db[((size_t)(p0 + y + 8 * j) << 6) + c0 + x] = t[x][y + 8 * j];
}

// ---------------------------------------------------------------- kernel 2
// One block per 32x4 tile. 128 threads = one pixel each.
__global__ __launch_bounds__(128)
void raster_kernel(const float* __restrict__ pts, float* __restrict__ out)
{
    __shared__ float4 sc[CAP];    // candidates: (x, y, z, bitcast idx)
    __shared__ int    scnt;

    const int b    = blockIdx.x >> 7;           // / NT
    const int t    = blockIdx.x & (NT - 1);
    const int ty   = t >> 2;
    const int tx   = t & (NTX - 1);
    const int lane = threadIdx.x & (TW - 1);
    const int row  = threadIdx.x >> 5;
    const int w    = tx * TW + lane;
    const int h    = ty * TH + row;

    if (threadIdx.x == 0) scnt = 0;
    __syncthreads();

    // tile bounds in NDC (ndc(w) = 1-(2w+1)/128, decreasing)
    const float x_hi = 1.0f - (2.0f * (tx * TW) + 1.0f) / 128.0f + RADM;
    const float x_lo = 1.0f - (2.0f * (tx * TW + TW - 1) + 1.0f) / 128.0f - RADM;
    const float y_hi = 1.0f - (2.0f * (ty * TH) + 1.0f) / 128.0f + RADM;
    const float y_lo = 1.0f - (2.0f * (ty * TH + TH - 1) + 1.0f) / 128.0f - RADM;

    // scan all points of this batch, warp-aggregated append of candidates
    const float* pb = pts + (size_t)b * PN * 3;
#pragma unroll
    for (int it = 0; it < PN / 128; ++it) {
        int p = it * 128 + threadIdx.x;
        float px = -pb[p * 3 + 0];   // sign flip from the torch forward
        float py = -pb[p * 3 + 1];
        float pz =  pb[p * 3 + 2];
        bool cand = (px >= x_lo) & (px <= x_hi) & (py >= y_lo) & (py <= y_hi);
        unsigned m = __ballot_sync(0xffffffffu, cand);
        if (cand) {
            int base;
            int nlead = __popc(m & ((1u << (threadIdx.x & 31)) - 1u));
            if (nlead == 0) base = atomicAdd(&scnt, __popc(m));
            base = __shfl_sync(m, base, __ffs(m) - 1);
            int slot = base + nlead;
            if (slot < CAP)
                sc[slot] = make_float4(px, py, pz, __int_as_float(p));
        }
    }
    __syncthreads();
    const int cnt = min(scnt, CAP);

    const float ndcx = 1.0f - (2.0f * (float)w + 1.0f) / 128.0f;
    const float ndcy = 1.0f - (2.0f * (float)h + 1.0f) / 128.0f;

    // register top-K sorted ascending by z
    float zb[KN], db[KN];
    int   ib[KN];
#pragma unroll
    for (int k = 0; k < KN; ++k) { zb[k] = BIGF; db[k] = 0.0f; ib[k] = 0; }

#pragma unroll 4
    for (int i = 0; i < cnt; ++i) {
        float4 pt = sc[i];
        float dx = ndcx - pt.x;
        float dy = ndcy - pt.y;
        // non-fused: match reference rounding at the radius discontinuity
        float d2 = __fadd_rn(__fmul_rn(dx, dx), __fmul_rn(dy, dy));
        if (d2 <= R2 && pt.z < zb[KN - 1]) {
            float cz = pt.z, cd = d2;
            int   ci = __float_as_int(pt.w);
            bool  ins = false;
#pragma unroll
            for (int k = 0; k < KN; ++k) {
                bool sw = ins | (cz < zb[k]);
                if (sw) {
                    float tz = zb[k]; zb[k] = cz; cz = tz;
                    float td = db[k]; db[k] = cd; cd = td;
                    int   ti = ib[k]; ib[k] = ci; ci = ti;
                    ins = true;
                }
            }
        }
    }

    // compositing weights: w_k = a_k * prod_{j<k}(1 - a_j)
    float wk[KN];
    float T = 1.0f;
#pragma unroll
    for (int k = 0; k < KN; ++k) {
        if (zb[k] < BIGF) {
            float dist = __fdiv_rn(db[k], R2);
            dist = fminf(fmaxf(dist, 0.001f), 1.0f);
            float a = 1.0f - __fsqrt_rn(dist);
            wk[k] = a * T;
            T = T * (1.0f - a);
        } else {
            wk[k] = 0.0f;
        }
    }

    // feature gather from srcT (contiguous 64 floats per point)
    float acc[CN];
#pragma unroll
    for (int c = 0; c < CN; ++c) acc[c] = 0.0f;

#pragma unroll
    for (int k = 0; k < KN; ++k) {
        if (wk[k] > 0.0f) {
            const float4* s4 =
                (const float4*)(d_srcT + (((size_t)b * PN + ib[k]) << 6));
            float wkk = wk[k];
#pragma unroll
            for (int j = 0; j < CN / 4; ++j) {
                float4 v = s4[j];
                acc[4 * j + 0] = fmaf(wkk, v.x, acc[4 * j + 0]);
                acc[4 * j + 1] = fmaf(wkk, v.y, acc[4 * j + 1]);
                acc[4 * j + 2] = fmaf(wkk, v.z, acc[4 * j + 2]);
                acc[4 * j + 3] = fmaf(wkk, v.w, acc[4 * j + 3]);
            }
        }
    }

    // out[b,c,h,w]; warp = one 32-px row -> coalesced 128B stores
    float* ob = out + (((size_t)b * CN) * SZ + h) * SZ + w;
#pragma unroll
    for (int c = 0; c < CN; ++c)
        ob[(size_t)c * SZ * SZ] = acc[c];
}

// ---------------------------------------------------------------- launch
extern "C" void kernel_launch(void* const* d_in, const int* in_sizes, int n_in,
                              void* d_out, int out_size)
{
    const float* pts = (const float*)d_in[0];  // [B,P,3]
    const float* src = (const float*)d_in[1];  // [B,C,P]
    float* out = (float*)d_out;                // [B,C,H,W]

    transpose_kernel<<<dim3(PN / 32, CN / 32, BN), dim3(32, 8)>>>(src);
    raster_kernel<<<BN * NT, 128>>>(pts, out);
}